// round 1
// baseline (speedup 1.0000x reference)
#include <cuda_runtime.h>
#include <math.h>

// Problem constants
#define DIM   1024
#define SEQ   2048
#define BATCH 2
#define NHEAD 16
#define HD    64
#define ROWS  (BATCH * SEQ)   // 4096

// ---------------------------------------------------------------------------
// Scratch buffers (allocation-free rule: __device__ globals)
// ---------------------------------------------------------------------------
__device__ float g_h1 [ROWS * DIM];        // LN1(x)
__device__ float g_qkv[ROWS * 3 * DIM];    // qkv projections
__device__ float g_att[ROWS * DIM];        // attention output (pre-proj)
__device__ float g_x2 [ROWS * DIM];        // x + attn_proj
__device__ float g_h2 [ROWS * DIM];        // LN2(x2)
__device__ float g_fc [ROWS * 4 * DIM];    // relu(h2 @ W_fc + b_fc)

// ---------------------------------------------------------------------------
// LayerNorm: one block per row, 256 threads, D=1024 (4 floats/thread)
// ---------------------------------------------------------------------------
__global__ void ln_kernel(const float* __restrict__ x,
                          const float* __restrict__ gamma,
                          const float* __restrict__ beta,
                          float* __restrict__ out) {
    const int row = blockIdx.x;
    const float* xr = x + (size_t)row * DIM;
    float4 v = ((const float4*)xr)[threadIdx.x];
    float s  = v.x + v.y + v.z + v.w;
    float s2 = v.x * v.x + v.y * v.y + v.z * v.z + v.w * v.w;

    #pragma unroll
    for (int o = 16; o > 0; o >>= 1) {
        s  += __shfl_down_sync(0xFFFFFFFFu, s,  o);
        s2 += __shfl_down_sync(0xFFFFFFFFu, s2, o);
    }
    __shared__ float rs[8], rs2[8];
    const int w = threadIdx.x >> 5, l = threadIdx.x & 31;
    if (l == 0) { rs[w] = s; rs2[w] = s2; }
    __syncthreads();
    if (threadIdx.x == 0) {
        float a = 0.f, b = 0.f;
        #pragma unroll
        for (int i = 0; i < 8; i++) { a += rs[i]; b += rs2[i]; }
        const float mu = a / DIM;
        rs[0]  = mu;
        rs2[0] = b / DIM - mu * mu;  // variance
    }
    __syncthreads();
    const float mu  = rs[0];
    const float inv = rsqrtf(rs2[0] + 1e-5f);
    float4 gv = ((const float4*)gamma)[threadIdx.x];
    float4 bv = ((const float4*)beta )[threadIdx.x];
    float4 o4;
    o4.x = (v.x - mu) * inv * gv.x + bv.x;
    o4.y = (v.y - mu) * inv * gv.y + bv.y;
    o4.z = (v.z - mu) * inv * gv.z + bv.z;
    o4.w = (v.w - mu) * inv * gv.w + bv.w;
    ((float4*)(out + (size_t)row * DIM))[threadIdx.x] = o4;
}

// ---------------------------------------------------------------------------
// SGEMM: C[M,N] = A[M,K] @ W[K,N] + bias (+relu) (+residual)
// BM=BN=64, BK=16, 256 threads, 4x4 per thread, fully float4 smem traffic.
// M,N multiples of 64; K multiple of 16 (holds for all 4 GEMMs here).
// ---------------------------------------------------------------------------
template <bool RELU, bool RESID>
__global__ void sgemm_kernel(const float* __restrict__ A,
                             const float* __restrict__ W,
                             const float* __restrict__ bias,
                             const float* __restrict__ resid,
                             float* __restrict__ C,
                             int M, int N, int K) {
    __shared__ float As[16][64];   // As[k][m] (transposed)
    __shared__ float Bs[16][64];   // Bs[k][n]

    const int tid = threadIdx.x;
    const int tx = tid & 15, ty = tid >> 4;
    const int m0 = blockIdx.y * 64, n0 = blockIdx.x * 64;

    const int arow = tid >> 2;            // 0..63
    const int acol = (tid & 3) * 4;       // 0,4,8,12
    const int brow = tid >> 4;            // 0..15
    const int bcol = (tid & 15) * 4;      // 0..60

    float acc[4][4] = {};

    for (int k0 = 0; k0 < K; k0 += 16) {
        float4 av = *(const float4*)(A + (size_t)(m0 + arow) * K + k0 + acol);
        As[acol + 0][arow] = av.x;
        As[acol + 1][arow] = av.y;
        As[acol + 2][arow] = av.z;
        As[acol + 3][arow] = av.w;
        float4 bv = *(const float4*)(W + (size_t)(k0 + brow) * N + n0 + bcol);
        *(float4*)&Bs[brow][bcol] = bv;
        __syncthreads();

        #pragma unroll
        for (int kk = 0; kk < 16; kk++) {
            float4 a4 = *(const float4*)&As[kk][ty * 4];
            float4 b4 = *(const float4*)&Bs[kk][tx * 4];
            acc[0][0] += a4.x * b4.x; acc[0][1] += a4.x * b4.y;
            acc[0][2] += a4.x * b4.z; acc[0][3] += a4.x * b4.w;
            acc[1][0] += a4.y * b4.x; acc[1][1] += a4.y * b4.y;
            acc[1][2] += a4.y * b4.z; acc[1][3] += a4.y * b4.w;
            acc[2][0] += a4.z * b4.x; acc[2][1] += a4.z * b4.y;
            acc[2][2] += a4.z * b4.z; acc[2][3] += a4.z * b4.w;
            acc[3][0] += a4.w * b4.x; acc[3][1] += a4.w * b4.y;
            acc[3][2] += a4.w * b4.z; acc[3][3] += a4.w * b4.w;
        }
        __syncthreads();
    }

    const float4 bvec = *(const float4*)(bias + n0 + tx * 4);
    #pragma unroll
    for (int i = 0; i < 4; i++) {
        const int m = m0 + ty * 4 + i;
        float4 r;
        r.x = acc[i][0] + bvec.x;
        r.y = acc[i][1] + bvec.y;
        r.z = acc[i][2] + bvec.z;
        r.w = acc[i][3] + bvec.w;
        if (RELU) {
            r.x = fmaxf(r.x, 0.f); r.y = fmaxf(r.y, 0.f);
            r.z = fmaxf(r.z, 0.f); r.w = fmaxf(r.w, 0.f);
        }
        if (RESID) {
            float4 rv = *(const float4*)(resid + (size_t)m * N + n0 + tx * 4);
            r.x += rv.x; r.y += rv.y; r.z += rv.z; r.w += rv.w;
        }
        *(float4*)(C + (size_t)m * N + n0 + tx * 4) = r;
    }
}

// ---------------------------------------------------------------------------
// Causal flash attention, fp32, hd=64. 64 queries x 64 keys per tile.
// qkv layout: [B, S, 3*DIM]; q at col h*64, k at DIM + h*64, v at 2*DIM + h*64.
// Output to att[B,S,DIM] in (h*64 + d) layout.
// ---------------------------------------------------------------------------
#define FPAD 68
__global__ void flash_kernel(const float* __restrict__ qkv,
                             float* __restrict__ out) {
    extern __shared__ float smem[];
    float* Qs    = smem;              // [64][FPAD], Qs[d][r]
    float* Ks    = Qs + 64 * FPAD;    // [64][FPAD], Ks[d][c]
    float* Vs    = Ks + 64 * FPAD;    // [64][FPAD], Vs[kv][d]
    float* Ss    = Vs + 64 * FPAD;    // [64][FPAD], Ss[r][kv]
    float* smax  = Ss + 64 * FPAD;    // [64]
    float* ssum  = smax + 64;         // [64]
    float* salpha = ssum + 64;        // [64]

    const int tid = threadIdx.x;
    const int tx = tid & 15, ty = tid >> 4;
    const int b = blockIdx.y >> 4, h = blockIdx.y & 15;
    const int qt = blockIdx.x;
    const int q0 = qt * 64;
    const size_t rstride = 3 * DIM;

    const float* qb = qkv + (size_t)b * SEQ * rstride + h * HD;
    const float* kb = qb + DIM;
    const float* vb = qb + 2 * DIM;

    // Load Q tile transposed: Qs[d][r]
    #pragma unroll
    for (int it = 0; it < 4; it++) {
        const int idx = it * 256 + tid;
        const int r = idx >> 4, c = (idx & 15) * 4;
        float4 v = *(const float4*)(qb + (size_t)(q0 + r) * rstride + c);
        Qs[(c + 0) * FPAD + r] = v.x;
        Qs[(c + 1) * FPAD + r] = v.y;
        Qs[(c + 2) * FPAD + r] = v.z;
        Qs[(c + 3) * FPAD + r] = v.w;
    }
    if (tid < 64) { smax[tid] = -1e30f; ssum[tid] = 0.f; }

    float o[4][4] = {};

    for (int jt = 0; jt <= qt; jt++) {
        const int kv0 = jt * 64;
        // Load K (transposed) and V (natural)
        #pragma unroll
        for (int it = 0; it < 4; it++) {
            const int idx = it * 256 + tid;
            const int r = idx >> 4, c = (idx & 15) * 4;
            float4 kv = *(const float4*)(kb + (size_t)(kv0 + r) * rstride + c);
            Ks[(c + 0) * FPAD + r] = kv.x;
            Ks[(c + 1) * FPAD + r] = kv.y;
            Ks[(c + 2) * FPAD + r] = kv.z;
            Ks[(c + 3) * FPAD + r] = kv.w;
            float4 vv = *(const float4*)(vb + (size_t)(kv0 + r) * rstride + c);
            *(float4*)(Vs + r * FPAD + c) = vv;
        }
        __syncthreads();

        // S = Q K^T / sqrt(hd) with causal mask on the diagonal tile
        float acc[4][4] = {};
        #pragma unroll 4
        for (int kk = 0; kk < 64; kk++) {
            const float a0 = Qs[kk * FPAD + ty * 4 + 0];
            const float a1 = Qs[kk * FPAD + ty * 4 + 1];
            const float a2 = Qs[kk * FPAD + ty * 4 + 2];
            const float a3 = Qs[kk * FPAD + ty * 4 + 3];
            const float b0 = Ks[kk * FPAD + tx * 4 + 0];
            const float b1 = Ks[kk * FPAD + tx * 4 + 1];
            const float b2 = Ks[kk * FPAD + tx * 4 + 2];
            const float b3 = Ks[kk * FPAD + tx * 4 + 3];
            acc[0][0] += a0 * b0; acc[0][1] += a0 * b1; acc[0][2] += a0 * b2; acc[0][3] += a0 * b3;
            acc[1][0] += a1 * b0; acc[1][1] += a1 * b1; acc[1][2] += a1 * b2; acc[1][3] += a1 * b3;
            acc[2][0] += a2 * b0; acc[2][1] += a2 * b1; acc[2][2] += a2 * b2; acc[2][3] += a2 * b3;
            acc[3][0] += a3 * b0; acc[3][1] += a3 * b1; acc[3][2] += a3 * b2; acc[3][3] += a3 * b3;
        }
        #pragma unroll
        for (int i = 0; i < 4; i++) {
            #pragma unroll
            for (int j = 0; j < 4; j++) {
                float sv = acc[i][j] * 0.125f;   // 1/sqrt(64)
                if (jt == qt && (kv0 + tx * 4 + j) > (q0 + ty * 4 + i)) sv = -1e30f;
                Ss[(ty * 4 + i) * FPAD + tx * 4 + j] = sv;
            }
        }
        __syncthreads();

        // Online-softmax row pass (one thread per query row)
        if (tid < 64) {
            const int r = tid;
            const float mo = smax[r];
            float mx = mo;
            #pragma unroll 8
            for (int j = 0; j < 64; j++) mx = fmaxf(mx, Ss[r * FPAD + j]);
            const float alpha = __expf(mo - mx);
            float lsum = 0.f;
            #pragma unroll 8
            for (int j = 0; j < 64; j++) {
                const float p = __expf(Ss[r * FPAD + j] - mx);
                Ss[r * FPAD + j] = p;
                lsum += p;
            }
            smax[r] = mx;
            ssum[r] = ssum[r] * alpha + lsum;
            salpha[r] = alpha;
        }
        __syncthreads();

        // O = alpha*O + P @ V
        float al[4];
        #pragma unroll
        for (int i = 0; i < 4; i++) {
            al[i] = salpha[ty * 4 + i];
            o[i][0] *= al[i]; o[i][1] *= al[i]; o[i][2] *= al[i]; o[i][3] *= al[i];
        }
        #pragma unroll 4
        for (int kk = 0; kk < 64; kk++) {
            const float p0 = Ss[(ty * 4 + 0) * FPAD + kk];
            const float p1 = Ss[(ty * 4 + 1) * FPAD + kk];
            const float p2 = Ss[(ty * 4 + 2) * FPAD + kk];
            const float p3 = Ss[(ty * 4 + 3) * FPAD + kk];
            const float4 v4 = *(const float4*)(Vs + kk * FPAD + tx * 4);
            o[0][0] += p0 * v4.x; o[0][1] += p0 * v4.y; o[0][2] += p0 * v4.z; o[0][3] += p0 * v4.w;
            o[1][0] += p1 * v4.x; o[1][1] += p1 * v4.y; o[1][2] += p1 * v4.z; o[1][3] += p1 * v4.w;
            o[2][0] += p2 * v4.x; o[2][1] += p2 * v4.y; o[2][2] += p2 * v4.z; o[2][3] += p2 * v4.w;
            o[3][0] += p3 * v4.x; o[3][1] += p3 * v4.y; o[3][2] += p3 * v4.z; o[3][3] += p3 * v4.w;
        }
        __syncthreads();
    }

    #pragma unroll
    for (int i = 0; i < 4; i++) {
        const float invl = 1.f / ssum[ty * 4 + i];
        const int q = q0 + ty * 4 + i;
        float4 r4 = make_float4(o[i][0] * invl, o[i][1] * invl,
                                o[i][2] * invl, o[i][3] * invl);
        *(float4*)(out + ((size_t)b * SEQ + q) * DIM + h * HD + tx * 4) = r4;
    }
}

// ---------------------------------------------------------------------------
// Launch
// ---------------------------------------------------------------------------
extern "C" void kernel_launch(void* const* d_in, const int* in_sizes, int n_in,
                              void* d_out, int out_size) {
    const float* x      = (const float*)d_in[0];
    const float* ln1_g  = (const float*)d_in[1];
    const float* ln1_b  = (const float*)d_in[2];
    const float* ln2_g  = (const float*)d_in[3];
    const float* ln2_b  = (const float*)d_in[4];
    const float* W_qkv  = (const float*)d_in[5];
    const float* b_qkv  = (const float*)d_in[6];
    const float* W_proj = (const float*)d_in[7];
    const float* b_proj = (const float*)d_in[8];
    const float* W_fc   = (const float*)d_in[9];
    const float* b_fc   = (const float*)d_in[10];
    const float* W_out  = (const float*)d_in[11];
    const float* b_out  = (const float*)d_in[12];
    float* out = (float*)d_out;

    float *h1, *qkv, *att, *x2, *h2, *fc;
    cudaGetSymbolAddress((void**)&h1,  g_h1);
    cudaGetSymbolAddress((void**)&qkv, g_qkv);
    cudaGetSymbolAddress((void**)&att, g_att);
    cudaGetSymbolAddress((void**)&x2,  g_x2);
    cudaGetSymbolAddress((void**)&h2,  g_h2);
    cudaGetSymbolAddress((void**)&fc,  g_fc);

    const int flash_smem = (4 * 64 * FPAD + 3 * 64) * (int)sizeof(float);
    cudaFuncSetAttribute(flash_kernel,
                         cudaFuncAttributeMaxDynamicSharedMemorySize, flash_smem);

    // 1) h1 = LN1(x)
    ln_kernel<<<ROWS, 256>>>(x, ln1_g, ln1_b, h1);

    // 2) qkv = h1 @ W_qkv + b_qkv      [4096 x 3072], K=1024
    sgemm_kernel<false, false><<<dim3(3 * DIM / 64, ROWS / 64), 256>>>(
        h1, W_qkv, b_qkv, nullptr, qkv, ROWS, 3 * DIM, DIM);

    // 3) att = causal_attention(qkv)
    flash_kernel<<<dim3(SEQ / 64, BATCH * NHEAD), 256, flash_smem>>>(qkv, att);

    // 4) x2 = att @ W_proj + b_proj + x
    sgemm_kernel<false, true><<<dim3(DIM / 64, ROWS / 64), 256>>>(
        att, W_proj, b_proj, x, x2, ROWS, DIM, DIM);

    // 5) h2 = LN2(x2)
    ln_kernel<<<ROWS, 256>>>(x2, ln2_g, ln2_b, h2);

    // 6) fc = relu(h2 @ W_fc + b_fc)   [4096 x 4096], K=1024
    sgemm_kernel<true, false><<<dim3(4 * DIM / 64, ROWS / 64), 256>>>(
        h2, W_fc, b_fc, nullptr, fc, ROWS, 4 * DIM, DIM);

    // 7) out = fc @ W_out + b_out + x2 [4096 x 1024], K=4096
    sgemm_kernel<false, true><<<dim3(DIM / 64, ROWS / 64), 256>>>(
        fc, W_out, b_out, x2, out, ROWS, DIM, 4 * DIM);
}

// round 5
// speedup vs baseline: 2.1091x; 2.1091x over previous
#include <cuda_runtime.h>
#include <cuda_bf16.h>
#include <cstdint>
#include <math.h>

// Problem constants
#define DIM   1024
#define SEQ   2048
#define BATCH 2
#define NHEAD 16
#define HD    64
#define ROWS  (BATCH * SEQ)   // 4096

// ---------------------------------------------------------------------------
// cp.async helpers (sm_80+, no arch-specific 'a' features)
// ---------------------------------------------------------------------------
__device__ __forceinline__ uint32_t smem_u32(const void* p) {
    uint32_t a;
    asm("{ .reg .u64 t; cvta.to.shared.u64 t, %1; cvt.u32.u64 %0, t; }" : "=r"(a) : "l"(p));
    return a;
}
#define CP_ASYNC16(sm, g) \
    asm volatile("cp.async.cg.shared.global [%0], [%1], 16;" :: "r"((uint32_t)(sm)), "l"(g) : "memory")
#define CP_COMMIT() asm volatile("cp.async.commit_group;" ::: "memory")
#define CP_WAIT1()  asm volatile("cp.async.wait_group 1;" ::: "memory")

// bf16 mma.sync m16n8k16, fp32 accumulate (portable tensor-core path)
__device__ __forceinline__ void mma16816(float* c, const uint32_t* a, const uint32_t* b) {
    asm volatile(
        "mma.sync.aligned.m16n8k16.row.col.f32.bf16.bf16.f32 "
        "{%0,%1,%2,%3}, {%4,%5,%6,%7}, {%8,%9}, {%0,%1,%2,%3};"
        : "+f"(c[0]), "+f"(c[1]), "+f"(c[2]), "+f"(c[3])
        : "r"(a[0]), "r"(a[1]), "r"(a[2]), "r"(a[3]), "r"(b[0]), "r"(b[1]));
}

// ---------------------------------------------------------------------------
// Scratch (allocation-free rule: __device__ globals)
// ---------------------------------------------------------------------------
__device__ __nv_bfloat16 g_h1_hi[ROWS * DIM];
__device__ __nv_bfloat16 g_h1_lo[ROWS * DIM];
__device__ float         g_qkv  [ROWS * 3 * DIM];
__device__ float         g_att  [ROWS * DIM];
__device__ __nv_bfloat16 g_att_hi[ROWS * DIM];
__device__ __nv_bfloat16 g_att_lo[ROWS * DIM];
__device__ float         g_x2   [ROWS * DIM];
__device__ __nv_bfloat16 g_h2_hi[ROWS * DIM];
__device__ __nv_bfloat16 g_h2_lo[ROWS * DIM];
__device__ __nv_bfloat16 g_fc_hi[ROWS * 4 * DIM];
__device__ __nv_bfloat16 g_fc_lo[ROWS * 4 * DIM];
// Transposed weights [N, K] bf16 hi/lo
__device__ __nv_bfloat16 g_wqkv_hi[3 * DIM * DIM];
__device__ __nv_bfloat16 g_wqkv_lo[3 * DIM * DIM];
__device__ __nv_bfloat16 g_wproj_hi[DIM * DIM];
__device__ __nv_bfloat16 g_wproj_lo[DIM * DIM];
__device__ __nv_bfloat16 g_wfc_hi[4 * DIM * DIM];
__device__ __nv_bfloat16 g_wfc_lo[4 * DIM * DIM];
__device__ __nv_bfloat16 g_wout_hi[DIM * 4 * DIM];
__device__ __nv_bfloat16 g_wout_lo[DIM * 4 * DIM];

__device__ __forceinline__ void split_bf16(float v, __nv_bfloat16& h, __nv_bfloat16& l) {
    h = __float2bfloat16(v);
    l = __float2bfloat16(v - __bfloat162float(h));
}

// ---------------------------------------------------------------------------
// Weight transpose + hi/lo split: W[K,N] fp32 -> Wt_hi/lo [N,K] bf16
// ---------------------------------------------------------------------------
__global__ void wconv_kernel(const float* __restrict__ W,
                             __nv_bfloat16* __restrict__ Wt_hi,
                             __nv_bfloat16* __restrict__ Wt_lo,
                             int K, int N) {
    __shared__ float t[32][33];
    const int tx = threadIdx.x & 31, ty = threadIdx.x >> 5;   // 32x8
    const int k0 = blockIdx.y * 32, n0 = blockIdx.x * 32;
    #pragma unroll
    for (int i = 0; i < 4; i++)
        t[ty + i * 8][tx] = W[(size_t)(k0 + ty + i * 8) * N + n0 + tx];
    __syncthreads();
    #pragma unroll
    for (int i = 0; i < 4; i++) {
        const int n = ty + i * 8;
        const float v = t[tx][n];
        __nv_bfloat16 h, l; split_bf16(v, h, l);
        const size_t o = (size_t)(n0 + n) * K + k0 + tx;
        Wt_hi[o] = h; Wt_lo[o] = l;
    }
}

// ---------------------------------------------------------------------------
// Elementwise fp32 -> hi/lo split
// ---------------------------------------------------------------------------
__global__ void split_kernel(const float* __restrict__ in,
                             __nv_bfloat16* __restrict__ hi,
                             __nv_bfloat16* __restrict__ lo, int n) {
    const int i = (blockIdx.x * blockDim.x + threadIdx.x) * 4;
    if (i >= n) return;
    float4 v = *(const float4*)(in + i);
    __nv_bfloat16 h0, l0, h1, l1, h2, l2, h3, l3;
    split_bf16(v.x, h0, l0); split_bf16(v.y, h1, l1);
    split_bf16(v.z, h2, l2); split_bf16(v.w, h3, l3);
    *(__nv_bfloat162*)(hi + i)     = __nv_bfloat162(h0, h1);
    *(__nv_bfloat162*)(hi + i + 2) = __nv_bfloat162(h2, h3);
    *(__nv_bfloat162*)(lo + i)     = __nv_bfloat162(l0, l1);
    *(__nv_bfloat162*)(lo + i + 2) = __nv_bfloat162(l2, l3);
}

// ---------------------------------------------------------------------------
// LayerNorm emitting hi/lo bf16
// ---------------------------------------------------------------------------
__global__ void ln_split_kernel(const float* __restrict__ x,
                                const float* __restrict__ gamma,
                                const float* __restrict__ beta,
                                __nv_bfloat16* __restrict__ hi,
                                __nv_bfloat16* __restrict__ lo) {
    const int row = blockIdx.x;
    const float* xr = x + (size_t)row * DIM;
    float4 v = ((const float4*)xr)[threadIdx.x];
    float s  = v.x + v.y + v.z + v.w;
    float s2 = v.x * v.x + v.y * v.y + v.z * v.z + v.w * v.w;
    #pragma unroll
    for (int o = 16; o > 0; o >>= 1) {
        s  += __shfl_down_sync(0xFFFFFFFFu, s,  o);
        s2 += __shfl_down_sync(0xFFFFFFFFu, s2, o);
    }
    __shared__ float rs[8], rs2[8];
    const int w = threadIdx.x >> 5, l = threadIdx.x & 31;
    if (l == 0) { rs[w] = s; rs2[w] = s2; }
    __syncthreads();
    if (threadIdx.x == 0) {
        float a = 0.f, b = 0.f;
        #pragma unroll
        for (int i = 0; i < 8; i++) { a += rs[i]; b += rs2[i]; }
        const float mu = a / DIM;
        rs[0] = mu; rs2[0] = b / DIM - mu * mu;
    }
    __syncthreads();
    const float mu  = rs[0];
    const float inv = rsqrtf(rs2[0] + 1e-5f);
    float4 gv = ((const float4*)gamma)[threadIdx.x];
    float4 bv = ((const float4*)beta )[threadIdx.x];
    float y0 = (v.x - mu) * inv * gv.x + bv.x;
    float y1 = (v.y - mu) * inv * gv.y + bv.y;
    float y2 = (v.z - mu) * inv * gv.z + bv.z;
    float y3 = (v.w - mu) * inv * gv.w + bv.w;
    __nv_bfloat16 h0, l0, h1, l1, h2, l2, h3, l3;
    split_bf16(y0, h0, l0); split_bf16(y1, h1, l1);
    split_bf16(y2, h2, l2); split_bf16(y3, h3, l3);
    const size_t o = (size_t)row * DIM + threadIdx.x * 4;
    *(__nv_bfloat162*)(hi + o)     = __nv_bfloat162(h0, h1);
    *(__nv_bfloat162*)(hi + o + 2) = __nv_bfloat162(h2, h3);
    *(__nv_bfloat162*)(lo + o)     = __nv_bfloat162(l0, l1);
    *(__nv_bfloat162*)(lo + o + 2) = __nv_bfloat162(l2, l3);
}

// ---------------------------------------------------------------------------
// mma.sync GEMM: C[M,N] = (A_hi+A_lo)[M,K] @ (B_hi+B_lo)^T  (B stored [N,K])
// CTA tile 128x128, 256 threads = 8 warps (2m x 4n), warp tile 64x32.
// K chunks of 32 bf16, double-buffered cp.async.
// smem tiles: 128 rows x 32 bf16, rows padded to 80B (conflict-free frag LDS).
// EPI: 0 = fp32+bias, 1 = fp32+bias+resid, 2 = relu(x+bias) -> hi/lo split
// ---------------------------------------------------------------------------
#define ROW_B    80                  // 64B data + 16B pad per row
#define TILE_B   (128 * ROW_B)       // 10240 B per tile
#define STAGE_B  (4 * TILE_B)        // Ah, Al, Bh, Bl = 40960 B
#define GEMM_SMEM (2 * STAGE_B)      // 81920 B

template <int EPI>
__global__ void __launch_bounds__(256, 2)
tc_gemm_kernel(const __nv_bfloat16* __restrict__ A_hi,
               const __nv_bfloat16* __restrict__ A_lo,
               const __nv_bfloat16* __restrict__ B_hi,
               const __nv_bfloat16* __restrict__ B_lo,
               const float* __restrict__ bias,
               const float* __restrict__ resid,
               float* __restrict__ C,
               __nv_bfloat16* __restrict__ C_hi,
               __nv_bfloat16* __restrict__ C_lo,
               int M, int N, int K) {
    extern __shared__ char smem[];
    const uint32_t sb = smem_u32(smem);
    const int tid = threadIdx.x, wid = tid >> 5, lid = tid & 31;
    const int g = lid >> 2, tig = lid & 3;          // groupID, thread-in-group
    const int wm = (wid & 1) * 64, wn = (wid >> 1) * 32;
    const int m0 = blockIdx.y * 128, n0 = blockIdx.x * 128;

    const __nv_bfloat16* parts[4] = { A_hi, A_lo, B_hi, B_lo };
    const int NC = K >> 5;   // K chunks of 32

    auto load_chunk = [&](int kc, int s) {
        const int k0 = kc << 5;
        #pragma unroll
        for (int p = 0; p < 4; p++) {
            const __nv_bfloat16* src = parts[p];
            const int rbase = (p < 2) ? m0 : n0;
            const uint32_t pb = sb + s * STAGE_B + p * TILE_B;
            #pragma unroll
            for (int i = 0; i < 2; i++) {
                const int idx = i * 256 + tid;       // 0..511
                const int r = idx >> 2, c = idx & 3;
                const __nv_bfloat16* gp = src + (size_t)(rbase + r) * K + k0 + c * 8;
                CP_ASYNC16(pb + r * ROW_B + c * 16, gp);
            }
        }
        CP_COMMIT();
    };

    float acc[4][4][4] = {};

    load_chunk(0, 0);
    load_chunk(1, 1);

    for (int kc = 0; kc < NC; kc++) {
        CP_WAIT1();
        __syncthreads();
        const int s = kc & 1;
        const uint32_t Ah = sb + s * STAGE_B;
        const uint32_t Al = Ah + TILE_B;
        const uint32_t Bh = Ah + 2 * TILE_B;
        const uint32_t Bl = Ah + 3 * TILE_B;

        #pragma unroll
        for (int ks = 0; ks < 2; ks++) {
            const uint32_t kbyte = ks * 32 + tig * 4;   // (ks*16 + tig*2) bf16
            // B fragments: all 4 n-tiles, hi+lo
            uint32_t bh[4][2], bl[4][2];
            #pragma unroll
            for (int j = 0; j < 4; j++) {
                const uint32_t ro = (uint32_t)(wn + j * 8 + g) * ROW_B + kbyte;
                bh[j][0] = *(const uint32_t*)(smem + (Bh - sb) + ro);
                bh[j][1] = *(const uint32_t*)(smem + (Bh - sb) + ro + 16);
                bl[j][0] = *(const uint32_t*)(smem + (Bl - sb) + ro);
                bl[j][1] = *(const uint32_t*)(smem + (Bl - sb) + ro + 16);
            }
            #pragma unroll
            for (int i = 0; i < 4; i++) {
                const uint32_t ro = (uint32_t)(wm + i * 16 + g) * ROW_B + kbyte;
                uint32_t ah[4], al[4];
                ah[0] = *(const uint32_t*)(smem + (Ah - sb) + ro);
                ah[1] = *(const uint32_t*)(smem + (Ah - sb) + ro + 8 * ROW_B);
                ah[2] = *(const uint32_t*)(smem + (Ah - sb) + ro + 16);
                ah[3] = *(const uint32_t*)(smem + (Ah - sb) + ro + 8 * ROW_B + 16);
                al[0] = *(const uint32_t*)(smem + (Al - sb) + ro);
                al[1] = *(const uint32_t*)(smem + (Al - sb) + ro + 8 * ROW_B);
                al[2] = *(const uint32_t*)(smem + (Al - sb) + ro + 16);
                al[3] = *(const uint32_t*)(smem + (Al - sb) + ro + 8 * ROW_B + 16);
                #pragma unroll
                for (int j = 0; j < 4; j++) {
                    mma16816(acc[i][j], ah, bh[j]);
                    mma16816(acc[i][j], ah, bl[j]);
                    mma16816(acc[i][j], al, bh[j]);
                }
            }
        }
        __syncthreads();
        if (kc + 2 < NC) load_chunk(kc + 2, s);
        else             CP_COMMIT();               // keep group accounting
    }

    // Epilogue
    #pragma unroll
    for (int i = 0; i < 4; i++) {
        const int row0 = m0 + wm + i * 16 + g;
        #pragma unroll
        for (int j = 0; j < 4; j++) {
            const int col = n0 + wn + j * 8 + tig * 2;
            const float2 b2 = *(const float2*)(bias + col);
            float v00 = acc[i][j][0] + b2.x;
            float v01 = acc[i][j][1] + b2.y;
            float v10 = acc[i][j][2] + b2.x;
            float v11 = acc[i][j][3] + b2.y;
            if (EPI == 2) {
                v00 = fmaxf(v00, 0.f); v01 = fmaxf(v01, 0.f);
                v10 = fmaxf(v10, 0.f); v11 = fmaxf(v11, 0.f);
                __nv_bfloat16 h0, l0, h1, l1;
                split_bf16(v00, h0, l0); split_bf16(v01, h1, l1);
                *(__nv_bfloat162*)(C_hi + (size_t)row0 * N + col) = __nv_bfloat162(h0, h1);
                *(__nv_bfloat162*)(C_lo + (size_t)row0 * N + col) = __nv_bfloat162(l0, l1);
                split_bf16(v10, h0, l0); split_bf16(v11, h1, l1);
                *(__nv_bfloat162*)(C_hi + (size_t)(row0 + 8) * N + col) = __nv_bfloat162(h0, h1);
                *(__nv_bfloat162*)(C_lo + (size_t)(row0 + 8) * N + col) = __nv_bfloat162(l0, l1);
            } else {
                if (EPI == 1) {
                    const float2 r0 = *(const float2*)(resid + (size_t)row0 * N + col);
                    const float2 r1 = *(const float2*)(resid + (size_t)(row0 + 8) * N + col);
                    v00 += r0.x; v01 += r0.y; v10 += r1.x; v11 += r1.y;
                }
                *(float2*)(C + (size_t)row0 * N + col)       = make_float2(v00, v01);
                *(float2*)(C + (size_t)(row0 + 8) * N + col) = make_float2(v10, v11);
            }
        }
    }
}

// ---------------------------------------------------------------------------
// Causal flash attention, fp32, hd=64 (unchanged, passing)
// ---------------------------------------------------------------------------
#define FPAD 68
__global__ void flash_kernel(const float* __restrict__ qkv,
                             float* __restrict__ out) {
    extern __shared__ float fsm[];
    float* Qs = fsm;
    float* Ks = Qs + 64 * FPAD;
    float* Vs = Ks + 64 * FPAD;
    float* Ss = Vs + 64 * FPAD;
    float* smax = Ss + 64 * FPAD;
    float* ssum = smax + 64;
    float* salpha = ssum + 64;

    const int tid = threadIdx.x;
    const int tx = tid & 15, ty = tid >> 4;
    const int b = blockIdx.y >> 4, h = blockIdx.y & 15;
    const int qt = blockIdx.x;
    const int q0 = qt * 64;
    const size_t rstride = 3 * DIM;

    const float* qb = qkv + (size_t)b * SEQ * rstride + h * HD;
    const float* kb = qb + DIM;
    const float* vb = qb + 2 * DIM;

    #pragma unroll
    for (int it = 0; it < 4; it++) {
        const int idx = it * 256 + tid;
        const int r = idx >> 4, c = (idx & 15) * 4;
        float4 v = *(const float4*)(qb + (size_t)(q0 + r) * rstride + c);
        Qs[(c + 0) * FPAD + r] = v.x;
        Qs[(c + 1) * FPAD + r] = v.y;
        Qs[(c + 2) * FPAD + r] = v.z;
        Qs[(c + 3) * FPAD + r] = v.w;
    }
    if (tid < 64) { smax[tid] = -1e30f; ssum[tid] = 0.f; }

    float o[4][4] = {};

    for (int jt = 0; jt <= qt; jt++) {
        const int kv0 = jt * 64;
        #pragma unroll
        for (int it = 0; it < 4; it++) {
            const int idx = it * 256 + tid;
            const int r = idx >> 4, c = (idx & 15) * 4;
            float4 kv = *(const float4*)(kb + (size_t)(kv0 + r) * rstride + c);
            Ks[(c + 0) * FPAD + r] = kv.x;
            Ks[(c + 1) * FPAD + r] = kv.y;
            Ks[(c + 2) * FPAD + r] = kv.z;
            Ks[(c + 3) * FPAD + r] = kv.w;
            float4 vv = *(const float4*)(vb + (size_t)(kv0 + r) * rstride + c);
            *(float4*)(Vs + r * FPAD + c) = vv;
        }
        __syncthreads();

        float acc[4][4] = {};
        #pragma unroll 4
        for (int kk = 0; kk < 64; kk++) {
            const float a0 = Qs[kk * FPAD + ty * 4 + 0];
            const float a1 = Qs[kk * FPAD + ty * 4 + 1];
            const float a2 = Qs[kk * FPAD + ty * 4 + 2];
            const float a3 = Qs[kk * FPAD + ty * 4 + 3];
            const float b0 = Ks[kk * FPAD + tx * 4 + 0];
            const float b1 = Ks[kk * FPAD + tx * 4 + 1];
            const float b2 = Ks[kk * FPAD + tx * 4 + 2];
            const float b3 = Ks[kk * FPAD + tx * 4 + 3];
            acc[0][0] += a0 * b0; acc[0][1] += a0 * b1; acc[0][2] += a0 * b2; acc[0][3] += a0 * b3;
            acc[1][0] += a1 * b0; acc[1][1] += a1 * b1; acc[1][2] += a1 * b2; acc[1][3] += a1 * b3;
            acc[2][0] += a2 * b0; acc[2][1] += a2 * b1; acc[2][2] += a2 * b2; acc[2][3] += a2 * b3;
            acc[3][0] += a3 * b0; acc[3][1] += a3 * b1; acc[3][2] += a3 * b2; acc[3][3] += a3 * b3;
        }
        #pragma unroll
        for (int i = 0; i < 4; i++)
            #pragma unroll
            for (int j = 0; j < 4; j++) {
                float sv = acc[i][j] * 0.125f;
                if (jt == qt && (kv0 + tx * 4 + j) > (q0 + ty * 4 + i)) sv = -1e30f;
                Ss[(ty * 4 + i) * FPAD + tx * 4 + j] = sv;
            }
        __syncthreads();

        if (tid < 64) {
            const int r = tid;
            const float mo = smax[r];
            float mx = mo;
            #pragma unroll 8
            for (int j = 0; j < 64; j++) mx = fmaxf(mx, Ss[r * FPAD + j]);
            const float alpha = __expf(mo - mx);
            float lsum = 0.f;
            #pragma unroll 8
            for (int j = 0; j < 64; j++) {
                const float p = __expf(Ss[r * FPAD + j] - mx);
                Ss[r * FPAD + j] = p;
                lsum += p;
            }
            smax[r] = mx;
            ssum[r] = ssum[r] * alpha + lsum;
            salpha[r] = alpha;
        }
        __syncthreads();

        float al[4];
        #pragma unroll
        for (int i = 0; i < 4; i++) {
            al[i] = salpha[ty * 4 + i];
            o[i][0] *= al[i]; o[i][1] *= al[i]; o[i][2] *= al[i]; o[i][3] *= al[i];
        }
        #pragma unroll 4
        for (int kk = 0; kk < 64; kk++) {
            const float p0 = Ss[(ty * 4 + 0) * FPAD + kk];
            const float p1 = Ss[(ty * 4 + 1) * FPAD + kk];
            const float p2 = Ss[(ty * 4 + 2) * FPAD + kk];
            const float p3 = Ss[(ty * 4 + 3) * FPAD + kk];
            const float4 v4 = *(const float4*)(Vs + kk * FPAD + tx * 4);
            o[0][0] += p0 * v4.x; o[0][1] += p0 * v4.y; o[0][2] += p0 * v4.z; o[0][3] += p0 * v4.w;
            o[1][0] += p1 * v4.x; o[1][1] += p1 * v4.y; o[1][2] += p1 * v4.z; o[1][3] += p1 * v4.w;
            o[2][0] += p2 * v4.x; o[2][1] += p2 * v4.y; o[2][2] += p2 * v4.z; o[2][3] += p2 * v4.w;
            o[3][0] += p3 * v4.x; o[3][1] += p3 * v4.y; o[3][2] += p3 * v4.z; o[3][3] += p3 * v4.w;
        }
        __syncthreads();
    }

    #pragma unroll
    for (int i = 0; i < 4; i++) {
        const float invl = 1.f / ssum[ty * 4 + i];
        const int q = q0 + ty * 4 + i;
        float4 r4 = make_float4(o[i][0] * invl, o[i][1] * invl,
                                o[i][2] * invl, o[i][3] * invl);
        *(float4*)(out + ((size_t)b * SEQ + q) * DIM + h * HD + tx * 4) = r4;
    }
}

// ---------------------------------------------------------------------------
// Launch
// ---------------------------------------------------------------------------
extern "C" void kernel_launch(void* const* d_in, const int* in_sizes, int n_in,
                              void* d_out, int out_size) {
    const float* x      = (const float*)d_in[0];
    const float* ln1_g  = (const float*)d_in[1];
    const float* ln1_b  = (const float*)d_in[2];
    const float* ln2_g  = (const float*)d_in[3];
    const float* ln2_b  = (const float*)d_in[4];
    const float* W_qkv  = (const float*)d_in[5];
    const float* b_qkv  = (const float*)d_in[6];
    const float* W_proj = (const float*)d_in[7];
    const float* b_proj = (const float*)d_in[8];
    const float* W_fc   = (const float*)d_in[9];
    const float* b_fc   = (const float*)d_in[10];
    const float* W_out  = (const float*)d_in[11];
    const float* b_out  = (const float*)d_in[12];
    float* out = (float*)d_out;

    __nv_bfloat16 *h1h, *h1l, *atth, *attl, *h2h, *h2l, *fch, *fcl;
    __nv_bfloat16 *wqh, *wql, *wph, *wpl, *wfh, *wfl, *woh, *wol;
    float *qkv, *att, *x2;
    cudaGetSymbolAddress((void**)&h1h, g_h1_hi);  cudaGetSymbolAddress((void**)&h1l, g_h1_lo);
    cudaGetSymbolAddress((void**)&qkv, g_qkv);
    cudaGetSymbolAddress((void**)&att, g_att);
    cudaGetSymbolAddress((void**)&atth, g_att_hi); cudaGetSymbolAddress((void**)&attl, g_att_lo);
    cudaGetSymbolAddress((void**)&x2,  g_x2);
    cudaGetSymbolAddress((void**)&h2h, g_h2_hi);  cudaGetSymbolAddress((void**)&h2l, g_h2_lo);
    cudaGetSymbolAddress((void**)&fch, g_fc_hi);  cudaGetSymbolAddress((void**)&fcl, g_fc_lo);
    cudaGetSymbolAddress((void**)&wqh, g_wqkv_hi); cudaGetSymbolAddress((void**)&wql, g_wqkv_lo);
    cudaGetSymbolAddress((void**)&wph, g_wproj_hi); cudaGetSymbolAddress((void**)&wpl, g_wproj_lo);
    cudaGetSymbolAddress((void**)&wfh, g_wfc_hi);  cudaGetSymbolAddress((void**)&wfl, g_wfc_lo);
    cudaGetSymbolAddress((void**)&woh, g_wout_hi); cudaGetSymbolAddress((void**)&wol, g_wout_lo);

    cudaFuncSetAttribute(tc_gemm_kernel<0>, cudaFuncAttributeMaxDynamicSharedMemorySize, GEMM_SMEM);
    cudaFuncSetAttribute(tc_gemm_kernel<1>, cudaFuncAttributeMaxDynamicSharedMemorySize, GEMM_SMEM);
    cudaFuncSetAttribute(tc_gemm_kernel<2>, cudaFuncAttributeMaxDynamicSharedMemorySize, GEMM_SMEM);
    const int flash_smem = (4 * 64 * FPAD + 3 * 64) * (int)sizeof(float);
    cudaFuncSetAttribute(flash_kernel, cudaFuncAttributeMaxDynamicSharedMemorySize, flash_smem);

    // Weight transpose + split (per launch; deterministic)
    wconv_kernel<<<dim3(3 * DIM / 32, DIM / 32), 256>>>(W_qkv, wqh, wql, DIM, 3 * DIM);
    wconv_kernel<<<dim3(DIM / 32, DIM / 32), 256>>>(W_proj, wph, wpl, DIM, DIM);
    wconv_kernel<<<dim3(4 * DIM / 32, DIM / 32), 256>>>(W_fc, wfh, wfl, DIM, 4 * DIM);
    wconv_kernel<<<dim3(DIM / 32, 4 * DIM / 32), 256>>>(W_out, woh, wol, 4 * DIM, DIM);

    // 1) h1 = LN1(x) -> hi/lo
    ln_split_kernel<<<ROWS, 256>>>(x, ln1_g, ln1_b, h1h, h1l);

    // 2) qkv = h1 @ W_qkv + b_qkv  (fp32)
    tc_gemm_kernel<0><<<dim3(3 * DIM / 128, ROWS / 128), 256, GEMM_SMEM>>>(
        h1h, h1l, wqh, wql, b_qkv, nullptr, qkv, nullptr, nullptr, ROWS, 3 * DIM, DIM);

    // 3) att = causal_attention(qkv)
    flash_kernel<<<dim3(SEQ / 64, BATCH * NHEAD), 256, flash_smem>>>(qkv, att);

    // 3b) att -> hi/lo
    split_kernel<<<(ROWS * DIM / 4 + 255) / 256, 256>>>(att, atth, attl, ROWS * DIM);

    // 4) x2 = att @ W_proj + b_proj + x
    tc_gemm_kernel<1><<<dim3(DIM / 128, ROWS / 128), 256, GEMM_SMEM>>>(
        atth, attl, wph, wpl, b_proj, x, x2, nullptr, nullptr, ROWS, DIM, DIM);

    // 5) h2 = LN2(x2) -> hi/lo
    ln_split_kernel<<<ROWS, 256>>>(x2, ln2_g, ln2_b, h2h, h2l);

    // 6) fc = relu(h2 @ W_fc + b_fc) -> hi/lo
    tc_gemm_kernel<2><<<dim3(4 * DIM / 128, ROWS / 128), 256, GEMM_SMEM>>>(
        h2h, h2l, wfh, wfl, b_fc, nullptr, nullptr, fch, fcl, ROWS, 4 * DIM, DIM);

    // 7) out = fc @ W_out + b_out + x2
    tc_gemm_kernel<1><<<dim3(DIM / 128, ROWS / 128), 256, GEMM_SMEM>>>(
        fch, fcl, woh, wol, b_out, x2, out, nullptr, nullptr, ROWS, DIM, 4 * DIM);
}

// round 6
// speedup vs baseline: 4.6736x; 2.2160x over previous
#include <cuda_runtime.h>
#include <cuda_bf16.h>
#include <cstdint>
#include <math.h>

// Problem constants
#define DIM   1024
#define SEQ   2048
#define BATCH 2
#define NHEAD 16
#define HD    64
#define ROWS  (BATCH * SEQ)   // 4096

// ---------------------------------------------------------------------------
// PTX helpers (sm_80-portable only; no arch-'a' features)
// ---------------------------------------------------------------------------
__device__ __forceinline__ uint32_t smem_u32(const void* p) {
    uint32_t a;
    asm("{ .reg .u64 t; cvta.to.shared.u64 t, %1; cvt.u32.u64 %0, t; }" : "=r"(a) : "l"(p));
    return a;
}
#define CP_ASYNC16(sm, g) \
    asm volatile("cp.async.cg.shared.global [%0], [%1], 16;" :: "r"((uint32_t)(sm)), "l"(g) : "memory")
#define CP_COMMIT() asm volatile("cp.async.commit_group;" ::: "memory")
#define CP_WAIT1()  asm volatile("cp.async.wait_group 1;" ::: "memory")
#define CP_WAIT0()  asm volatile("cp.async.wait_group 0;" ::: "memory")

#define LDSM_X4(R, addr) \
    asm volatile("ldmatrix.sync.aligned.m8n8.x4.shared.b16 {%0,%1,%2,%3}, [%4];" \
        : "=r"((R)[0]), "=r"((R)[1]), "=r"((R)[2]), "=r"((R)[3]) : "r"((uint32_t)(addr)))
#define LDSM_X4_T(R, addr) \
    asm volatile("ldmatrix.sync.aligned.m8n8.x4.trans.shared.b16 {%0,%1,%2,%3}, [%4];" \
        : "=r"((R)[0]), "=r"((R)[1]), "=r"((R)[2]), "=r"((R)[3]) : "r"((uint32_t)(addr)))

// bf16 mma.sync m16n8k16, fp32 accumulate
__device__ __forceinline__ void mma16816(float* c, const uint32_t* a, const uint32_t* b) {
    asm volatile(
        "mma.sync.aligned.m16n8k16.row.col.f32.bf16.bf16.f32 "
        "{%0,%1,%2,%3}, {%4,%5,%6,%7}, {%8,%9}, {%0,%1,%2,%3};"
        : "+f"(c[0]), "+f"(c[1]), "+f"(c[2]), "+f"(c[3])
        : "r"(a[0]), "r"(a[1]), "r"(a[2]), "r"(a[3]), "r"(b[0]), "r"(b[1]));
}

__device__ __forceinline__ uint32_t pack2bf(__nv_bfloat16 a, __nv_bfloat16 b) {
    __nv_bfloat162 t(a, b);
    return *reinterpret_cast<uint32_t*>(&t);
}
__device__ __forceinline__ void split_bf16(float v, __nv_bfloat16& h, __nv_bfloat16& l) {
    h = __float2bfloat16(v);
    l = __float2bfloat16(v - __bfloat162float(h));
}

// ---------------------------------------------------------------------------
// Scratch (allocation-free rule: __device__ globals)
// ---------------------------------------------------------------------------
__device__ __nv_bfloat16 g_h1_hi[ROWS * DIM];
__device__ __nv_bfloat16 g_h1_lo[ROWS * DIM];
__device__ __nv_bfloat16 g_qkv_hi[ROWS * 3 * DIM];
__device__ __nv_bfloat16 g_qkv_lo[ROWS * 3 * DIM];
__device__ __nv_bfloat16 g_att_hi[ROWS * DIM];
__device__ __nv_bfloat16 g_att_lo[ROWS * DIM];
__device__ float         g_x2   [ROWS * DIM];
__device__ __nv_bfloat16 g_h2_hi[ROWS * DIM];
__device__ __nv_bfloat16 g_h2_lo[ROWS * DIM];
__device__ __nv_bfloat16 g_fc_hi[ROWS * 4 * DIM];
__device__ __nv_bfloat16 g_fc_lo[ROWS * 4 * DIM];
// Transposed weights [N, K] bf16 hi/lo
__device__ __nv_bfloat16 g_wqkv_hi[3 * DIM * DIM];
__device__ __nv_bfloat16 g_wqkv_lo[3 * DIM * DIM];
__device__ __nv_bfloat16 g_wproj_hi[DIM * DIM];
__device__ __nv_bfloat16 g_wproj_lo[DIM * DIM];
__device__ __nv_bfloat16 g_wfc_hi[4 * DIM * DIM];
__device__ __nv_bfloat16 g_wfc_lo[4 * DIM * DIM];
__device__ __nv_bfloat16 g_wout_hi[DIM * 4 * DIM];
__device__ __nv_bfloat16 g_wout_lo[DIM * 4 * DIM];

// ---------------------------------------------------------------------------
// Weight transpose + hi/lo split: W[K,N] fp32 -> Wt_hi/lo [N,K] bf16
// ---------------------------------------------------------------------------
__global__ void wconv_kernel(const float* __restrict__ W,
                             __nv_bfloat16* __restrict__ Wt_hi,
                             __nv_bfloat16* __restrict__ Wt_lo,
                             int K, int N) {
    __shared__ float t[32][33];
    const int tx = threadIdx.x & 31, ty = threadIdx.x >> 5;   // 32x8
    const int k0 = blockIdx.y * 32, n0 = blockIdx.x * 32;
    #pragma unroll
    for (int i = 0; i < 4; i++)
        t[ty + i * 8][tx] = W[(size_t)(k0 + ty + i * 8) * N + n0 + tx];
    __syncthreads();
    #pragma unroll
    for (int i = 0; i < 4; i++) {
        const int n = ty + i * 8;
        const float v = t[tx][n];
        __nv_bfloat16 h, l; split_bf16(v, h, l);
        const size_t o = (size_t)(n0 + n) * K + k0 + tx;
        Wt_hi[o] = h; Wt_lo[o] = l;
    }
}

// ---------------------------------------------------------------------------
// LayerNorm emitting hi/lo bf16
// ---------------------------------------------------------------------------
__global__ void ln_split_kernel(const float* __restrict__ x,
                                const float* __restrict__ gamma,
                                const float* __restrict__ beta,
                                __nv_bfloat16* __restrict__ hi,
                                __nv_bfloat16* __restrict__ lo) {
    const int row = blockIdx.x;
    const float* xr = x + (size_t)row * DIM;
    float4 v = ((const float4*)xr)[threadIdx.x];
    float s  = v.x + v.y + v.z + v.w;
    float s2 = v.x * v.x + v.y * v.y + v.z * v.z + v.w * v.w;
    #pragma unroll
    for (int o = 16; o > 0; o >>= 1) {
        s  += __shfl_down_sync(0xFFFFFFFFu, s,  o);
        s2 += __shfl_down_sync(0xFFFFFFFFu, s2, o);
    }
    __shared__ float rs[8], rs2[8];
    const int w = threadIdx.x >> 5, l = threadIdx.x & 31;
    if (l == 0) { rs[w] = s; rs2[w] = s2; }
    __syncthreads();
    if (threadIdx.x == 0) {
        float a = 0.f, b = 0.f;
        #pragma unroll
        for (int i = 0; i < 8; i++) { a += rs[i]; b += rs2[i]; }
        const float mu = a / DIM;
        rs[0] = mu; rs2[0] = b / DIM - mu * mu;
    }
    __syncthreads();
    const float mu  = rs[0];
    const float inv = rsqrtf(rs2[0] + 1e-5f);
    float4 gv = ((const float4*)gamma)[threadIdx.x];
    float4 bv = ((const float4*)beta )[threadIdx.x];
    float y0 = (v.x - mu) * inv * gv.x + bv.x;
    float y1 = (v.y - mu) * inv * gv.y + bv.y;
    float y2 = (v.z - mu) * inv * gv.z + bv.z;
    float y3 = (v.w - mu) * inv * gv.w + bv.w;
    __nv_bfloat16 h0, l0, h1, l1, h2, l2, h3, l3;
    split_bf16(y0, h0, l0); split_bf16(y1, h1, l1);
    split_bf16(y2, h2, l2); split_bf16(y3, h3, l3);
    const size_t o = (size_t)row * DIM + threadIdx.x * 4;
    *(__nv_bfloat162*)(hi + o)     = __nv_bfloat162(h0, h1);
    *(__nv_bfloat162*)(hi + o + 2) = __nv_bfloat162(h2, h3);
    *(__nv_bfloat162*)(lo + o)     = __nv_bfloat162(l0, l1);
    *(__nv_bfloat162*)(lo + o + 2) = __nv_bfloat162(l2, l3);
}

// ---------------------------------------------------------------------------
// mma.sync GEMM: C[M,N] = (A_hi+A_lo)[M,K] @ (B_hi+B_lo)^T  (B stored [N,K])
// CTA tile 128x128, 256 threads = 8 warps (2m x 4n), warp tile 64x32.
// EPI: 0 = fp32+bias, 1 = fp32+bias+resid, 2 = relu(x+bias)->hi/lo,
//      3 = (x+bias)->hi/lo
// ---------------------------------------------------------------------------
#define ROW_B    80
#define TILE_B   (128 * ROW_B)
#define STAGE_B  (4 * TILE_B)
#define GEMM_SMEM (2 * STAGE_B)

template <int EPI>
__global__ void __launch_bounds__(256, 2)
tc_gemm_kernel(const __nv_bfloat16* __restrict__ A_hi,
               const __nv_bfloat16* __restrict__ A_lo,
               const __nv_bfloat16* __restrict__ B_hi,
               const __nv_bfloat16* __restrict__ B_lo,
               const float* __restrict__ bias,
               const float* __restrict__ resid,
               float* __restrict__ C,
               __nv_bfloat16* __restrict__ C_hi,
               __nv_bfloat16* __restrict__ C_lo,
               int M, int N, int K) {
    extern __shared__ char smem[];
    const uint32_t sb = smem_u32(smem);
    const int tid = threadIdx.x, wid = tid >> 5, lid = tid & 31;
    const int g = lid >> 2, tig = lid & 3;
    const int wm = (wid & 1) * 64, wn = (wid >> 1) * 32;
    const int m0 = blockIdx.y * 128, n0 = blockIdx.x * 128;

    const __nv_bfloat16* parts[4] = { A_hi, A_lo, B_hi, B_lo };
    const int NC = K >> 5;

    auto load_chunk = [&](int kc, int s) {
        const int k0 = kc << 5;
        #pragma unroll
        for (int p = 0; p < 4; p++) {
            const __nv_bfloat16* src = parts[p];
            const int rbase = (p < 2) ? m0 : n0;
            const uint32_t pb = sb + s * STAGE_B + p * TILE_B;
            #pragma unroll
            for (int i = 0; i < 2; i++) {
                const int idx = i * 256 + tid;
                const int r = idx >> 2, c = idx & 3;
                const __nv_bfloat16* gp = src + (size_t)(rbase + r) * K + k0 + c * 8;
                CP_ASYNC16(pb + r * ROW_B + c * 16, gp);
            }
        }
        CP_COMMIT();
    };

    float acc[4][4][4] = {};

    load_chunk(0, 0);
    load_chunk(1, 1);

    for (int kc = 0; kc < NC; kc++) {
        CP_WAIT1();
        __syncthreads();
        const int s = kc & 1;
        const uint32_t Ah = sb + s * STAGE_B;
        const uint32_t Al = Ah + TILE_B;
        const uint32_t Bh = Ah + 2 * TILE_B;
        const uint32_t Bl = Ah + 3 * TILE_B;

        #pragma unroll
        for (int ks = 0; ks < 2; ks++) {
            const uint32_t kbyte = ks * 32 + tig * 4;
            uint32_t bh[4][2], bl[4][2];
            #pragma unroll
            for (int j = 0; j < 4; j++) {
                const uint32_t ro = (uint32_t)(wn + j * 8 + g) * ROW_B + kbyte;
                bh[j][0] = *(const uint32_t*)(smem + (Bh - sb) + ro);
                bh[j][1] = *(const uint32_t*)(smem + (Bh - sb) + ro + 16);
                bl[j][0] = *(const uint32_t*)(smem + (Bl - sb) + ro);
                bl[j][1] = *(const uint32_t*)(smem + (Bl - sb) + ro + 16);
            }
            #pragma unroll
            for (int i = 0; i < 4; i++) {
                const uint32_t ro = (uint32_t)(wm + i * 16 + g) * ROW_B + kbyte;
                uint32_t ah[4], al[4];
                ah[0] = *(const uint32_t*)(smem + (Ah - sb) + ro);
                ah[1] = *(const uint32_t*)(smem + (Ah - sb) + ro + 8 * ROW_B);
                ah[2] = *(const uint32_t*)(smem + (Ah - sb) + ro + 16);
                ah[3] = *(const uint32_t*)(smem + (Ah - sb) + ro + 8 * ROW_B + 16);
                al[0] = *(const uint32_t*)(smem + (Al - sb) + ro);
                al[1] = *(const uint32_t*)(smem + (Al - sb) + ro + 8 * ROW_B);
                al[2] = *(const uint32_t*)(smem + (Al - sb) + ro + 16);
                al[3] = *(const uint32_t*)(smem + (Al - sb) + ro + 8 * ROW_B + 16);
                #pragma unroll
                for (int j = 0; j < 4; j++) {
                    mma16816(acc[i][j], ah, bh[j]);
                    mma16816(acc[i][j], ah, bl[j]);
                    mma16816(acc[i][j], al, bh[j]);
                }
            }
        }
        __syncthreads();
        if (kc + 2 < NC) load_chunk(kc + 2, s);
        else             CP_COMMIT();
    }

    // Epilogue
    #pragma unroll
    for (int i = 0; i < 4; i++) {
        const int row0 = m0 + wm + i * 16 + g;
        #pragma unroll
        for (int j = 0; j < 4; j++) {
            const int col = n0 + wn + j * 8 + tig * 2;
            const float2 b2 = *(const float2*)(bias + col);
            float v00 = acc[i][j][0] + b2.x;
            float v01 = acc[i][j][1] + b2.y;
            float v10 = acc[i][j][2] + b2.x;
            float v11 = acc[i][j][3] + b2.y;
            if (EPI >= 2) {
                if (EPI == 2) {
                    v00 = fmaxf(v00, 0.f); v01 = fmaxf(v01, 0.f);
                    v10 = fmaxf(v10, 0.f); v11 = fmaxf(v11, 0.f);
                }
                __nv_bfloat16 h0, l0, h1, l1;
                split_bf16(v00, h0, l0); split_bf16(v01, h1, l1);
                *(__nv_bfloat162*)(C_hi + (size_t)row0 * N + col) = __nv_bfloat162(h0, h1);
                *(__nv_bfloat162*)(C_lo + (size_t)row0 * N + col) = __nv_bfloat162(l0, l1);
                split_bf16(v10, h0, l0); split_bf16(v11, h1, l1);
                *(__nv_bfloat162*)(C_hi + (size_t)(row0 + 8) * N + col) = __nv_bfloat162(h0, h1);
                *(__nv_bfloat162*)(C_lo + (size_t)(row0 + 8) * N + col) = __nv_bfloat162(l0, l1);
            } else {
                if (EPI == 1) {
                    const float2 r0 = *(const float2*)(resid + (size_t)row0 * N + col);
                    const float2 r1 = *(const float2*)(resid + (size_t)(row0 + 8) * N + col);
                    v00 += r0.x; v01 += r0.y; v10 += r1.x; v11 += r1.y;
                }
                *(float2*)(C + (size_t)row0 * N + col)       = make_float2(v00, v01);
                *(float2*)(C + (size_t)(row0 + 8) * N + col) = make_float2(v10, v11);
            }
        }
    }
}

// ---------------------------------------------------------------------------
// Causal flash attention, bf16 mma.sync with hi/lo compensation, hd=64.
// 128 threads (4 warps), 64 q-rows per block, each warp 16 rows.
// Q fragments register-resident; K/V hi/lo double-buffered via cp.async.
// Writes att hi/lo bf16 directly (layout [B,S,D], head-major cols).
// ---------------------------------------------------------------------------
#define FROWB 144                    // 128B data + 16B pad per row
#define FTILE (64 * FROWB)           // 9216
#define FSTAGE (4 * FTILE)           // Kh,Kl,Vh,Vl = 36864
#define FLASH_SMEM (2 * FSTAGE)      // 73728

__global__ void __launch_bounds__(128)
flash_kernel(const __nv_bfloat16* __restrict__ qkv_hi,
             const __nv_bfloat16* __restrict__ qkv_lo,
             __nv_bfloat16* __restrict__ out_hi,
             __nv_bfloat16* __restrict__ out_lo) {
    extern __shared__ char fsm[];
    const uint32_t sb = smem_u32(fsm);
    const int tid = threadIdx.x, wid = tid >> 5, lid = tid & 31;
    const int g = lid >> 2, tig = lid & 3;
    const int lt = lid >> 3, lr = lid & 7;
    const int b = blockIdx.y >> 4, h = blockIdx.y & 15;
    const int qt = blockIdx.x, q0 = qt * 64, wq = wid * 16;
    const size_t rstride = 3 * DIM;
    const __nv_bfloat16* qh_g = qkv_hi + (size_t)b * SEQ * rstride + h * HD;
    const __nv_bfloat16* ql_g = qkv_lo + (size_t)b * SEQ * rstride + h * HD;

    // ---- Stage Q hi/lo into stage 0, load A-fragments, free the smem ----
    #pragma unroll
    for (int t = 0; t < 2; t++) {
        const __nv_bfloat16* src = t ? ql_g : qh_g;
        #pragma unroll
        for (int i = 0; i < 4; i++) {
            const int idx = i * 128 + tid;
            const int r = idx >> 3, c = idx & 7;
            CP_ASYNC16(sb + t * FTILE + r * FROWB + c * 16,
                       src + (size_t)(q0 + r) * rstride + c * 8);
        }
    }
    CP_COMMIT();
    CP_WAIT0();
    __syncthreads();

    uint32_t qfh[4][4], qfl[4][4];
    {
        const int row = wq + ((lt & 1) ? 8 : 0) + lr;
        #pragma unroll
        for (int kc = 0; kc < 4; kc++) {
            const int col = kc * 16 + ((lt & 2) ? 8 : 0);
            LDSM_X4(qfh[kc], sb + row * FROWB + col * 2);
            LDSM_X4(qfl[kc], sb + FTILE + row * FROWB + col * 2);
        }
    }
    __syncthreads();

    const __nv_bfloat16* srcs[4] = { qh_g + DIM, ql_g + DIM, qh_g + 2 * DIM, ql_g + 2 * DIM };
    auto load_kv = [&](int jt, int s) {
        const int kv0 = jt * 64;
        #pragma unroll
        for (int p = 0; p < 4; p++) {
            #pragma unroll
            for (int i = 0; i < 4; i++) {
                const int idx = i * 128 + tid;
                const int r = idx >> 3, c = idx & 7;
                CP_ASYNC16(sb + s * FSTAGE + p * FTILE + r * FROWB + c * 16,
                           srcs[p] + (size_t)(kv0 + r) * rstride + c * 8);
            }
        }
        CP_COMMIT();
    };

    float m0v = -1e30f, m1v = -1e30f, l0v = 0.f, l1v = 0.f;
    float oacc[8][4] = {};

    load_kv(0, 0);

    const int krow = ((lt & 2) ? 8 : 0) + lr;   // K ldmatrix: key within 16-blk
    const int kcol8 = (lt & 1) ? 8 : 0;         // K ldmatrix: hd offset
    const int vrow = ((lt & 1) ? 8 : 0) + lr;   // V ldmatrix: key within 16-blk
    const int vcol8 = (lt & 2) ? 8 : 0;         // V ldmatrix: hd offset

    for (int jt = 0; jt <= qt; jt++) {
        const int s = jt & 1;
        __syncthreads();                        // all readers of stage s^1 done
        if (jt < qt) load_kv(jt + 1, s ^ 1);
        else         CP_COMMIT();
        CP_WAIT1();
        __syncthreads();

        const uint32_t Kh = sb + s * FSTAGE;
        const uint32_t Kl = Kh + FTILE;
        const uint32_t Vh = Kh + 2 * FTILE;
        const uint32_t Vl = Kh + 3 * FTILE;

        // ---- S = Q K^T (QhKh + QhKl + QlKh) ----
        float sacc[8][4] = {};
        #pragma unroll
        for (int kc = 0; kc < 4; kc++) {
            #pragma unroll
            for (int np = 0; np < 4; np++) {
                const uint32_t ko = (uint32_t)(np * 16 + krow) * FROWB + (kc * 16 + kcol8) * 2;
                uint32_t kb[4];
                LDSM_X4(kb, Kh + ko);
                mma16816(sacc[2 * np],     qfh[kc], kb);
                mma16816(sacc[2 * np + 1], qfh[kc], kb + 2);
                mma16816(sacc[2 * np],     qfl[kc], kb);
                mma16816(sacc[2 * np + 1], qfl[kc], kb + 2);
                LDSM_X4(kb, Kl + ko);
                mma16816(sacc[2 * np],     qfh[kc], kb);
                mma16816(sacc[2 * np + 1], qfh[kc], kb + 2);
            }
        }

        // ---- causal mask (diag tile only) ----
        const int kv0 = jt * 64;
        const int row0 = q0 + wq + g, row1 = row0 + 8;
        if (jt == qt) {
            #pragma unroll
            for (int j = 0; j < 8; j++) {
                const int cb = kv0 + j * 8 + tig * 2;
                if (cb > row0)     sacc[j][0] = -1e30f;
                if (cb + 1 > row0) sacc[j][1] = -1e30f;
                if (cb > row1)     sacc[j][2] = -1e30f;
                if (cb + 1 > row1) sacc[j][3] = -1e30f;
            }
        }

        // ---- online softmax (raw-score units; scale folded into exp) ----
        float mx0 = m0v, mx1 = m1v;
        #pragma unroll
        for (int j = 0; j < 8; j++) {
            mx0 = fmaxf(mx0, fmaxf(sacc[j][0], sacc[j][1]));
            mx1 = fmaxf(mx1, fmaxf(sacc[j][2], sacc[j][3]));
        }
        mx0 = fmaxf(mx0, __shfl_xor_sync(0xFFFFFFFFu, mx0, 1));
        mx0 = fmaxf(mx0, __shfl_xor_sync(0xFFFFFFFFu, mx0, 2));
        mx1 = fmaxf(mx1, __shfl_xor_sync(0xFFFFFFFFu, mx1, 1));
        mx1 = fmaxf(mx1, __shfl_xor_sync(0xFFFFFFFFu, mx1, 2));
        const float al0 = __expf((m0v - mx0) * 0.125f);
        const float al1 = __expf((m1v - mx1) * 0.125f);
        m0v = mx0; m1v = mx1;

        float ls0 = 0.f, ls1 = 0.f;
        #pragma unroll
        for (int j = 0; j < 8; j++) {
            sacc[j][0] = __expf((sacc[j][0] - mx0) * 0.125f); ls0 += sacc[j][0];
            sacc[j][1] = __expf((sacc[j][1] - mx0) * 0.125f); ls0 += sacc[j][1];
            sacc[j][2] = __expf((sacc[j][2] - mx1) * 0.125f); ls1 += sacc[j][2];
            sacc[j][3] = __expf((sacc[j][3] - mx1) * 0.125f); ls1 += sacc[j][3];
        }
        ls0 += __shfl_xor_sync(0xFFFFFFFFu, ls0, 1);
        ls0 += __shfl_xor_sync(0xFFFFFFFFu, ls0, 2);
        ls1 += __shfl_xor_sync(0xFFFFFFFFu, ls1, 1);
        ls1 += __shfl_xor_sync(0xFFFFFFFFu, ls1, 2);
        l0v = l0v * al0 + ls0;
        l1v = l1v * al1 + ls1;

        #pragma unroll
        for (int j = 0; j < 8; j++) {
            oacc[j][0] *= al0; oacc[j][1] *= al0;
            oacc[j][2] *= al1; oacc[j][3] *= al1;
        }

        // ---- O += P V (PhVh + PhVl + PlVh) ----
        #pragma unroll
        for (int kk = 0; kk < 4; kk++) {
            uint32_t aph[4], apl[4];
            {
                __nv_bfloat16 h0, l0, h1, l1;
                split_bf16(sacc[2 * kk][0], h0, l0); split_bf16(sacc[2 * kk][1], h1, l1);
                aph[0] = pack2bf(h0, h1); apl[0] = pack2bf(l0, l1);
                split_bf16(sacc[2 * kk][2], h0, l0); split_bf16(sacc[2 * kk][3], h1, l1);
                aph[1] = pack2bf(h0, h1); apl[1] = pack2bf(l0, l1);
                split_bf16(sacc[2 * kk + 1][0], h0, l0); split_bf16(sacc[2 * kk + 1][1], h1, l1);
                aph[2] = pack2bf(h0, h1); apl[2] = pack2bf(l0, l1);
                split_bf16(sacc[2 * kk + 1][2], h0, l0); split_bf16(sacc[2 * kk + 1][3], h1, l1);
                aph[3] = pack2bf(h0, h1); apl[3] = pack2bf(l0, l1);
            }
            #pragma unroll
            for (int np = 0; np < 4; np++) {
                const uint32_t vo = (uint32_t)(kk * 16 + vrow) * FROWB + (np * 16 + vcol8) * 2;
                uint32_t vb[4];
                LDSM_X4_T(vb, Vh + vo);
                mma16816(oacc[2 * np],     aph, vb);
                mma16816(oacc[2 * np + 1], aph, vb + 2);
                mma16816(oacc[2 * np],     apl, vb);
                mma16816(oacc[2 * np + 1], apl, vb + 2);
                LDSM_X4_T(vb, Vl + vo);
                mma16816(oacc[2 * np],     aph, vb);
                mma16816(oacc[2 * np + 1], aph, vb + 2);
            }
        }
    }

    // ---- epilogue: divide by l, split hi/lo, store ----
    const float inv0 = 1.f / l0v, inv1 = 1.f / l1v;
    const size_t base0 = (size_t)(b * SEQ + q0 + wq + g) * DIM + h * HD;
    const size_t base1 = base0 + 8 * DIM;
    #pragma unroll
    for (int j = 0; j < 8; j++) {
        const int co = j * 8 + tig * 2;
        __nv_bfloat16 h0, lo0, h1, lo1;
        split_bf16(oacc[j][0] * inv0, h0, lo0);
        split_bf16(oacc[j][1] * inv0, h1, lo1);
        *(__nv_bfloat162*)(out_hi + base0 + co) = __nv_bfloat162(h0, h1);
        *(__nv_bfloat162*)(out_lo + base0 + co) = __nv_bfloat162(lo0, lo1);
        split_bf16(oacc[j][2] * inv1, h0, lo0);
        split_bf16(oacc[j][3] * inv1, h1, lo1);
        *(__nv_bfloat162*)(out_hi + base1 + co) = __nv_bfloat162(h0, h1);
        *(__nv_bfloat162*)(out_lo + base1 + co) = __nv_bfloat162(lo0, lo1);
    }
}

// ---------------------------------------------------------------------------
// Launch
// ---------------------------------------------------------------------------
extern "C" void kernel_launch(void* const* d_in, const int* in_sizes, int n_in,
                              void* d_out, int out_size) {
    const float* x      = (const float*)d_in[0];
    const float* ln1_g  = (const float*)d_in[1];
    const float* ln1_b  = (const float*)d_in[2];
    const float* ln2_g  = (const float*)d_in[3];
    const float* ln2_b  = (const float*)d_in[4];
    const float* W_qkv  = (const float*)d_in[5];
    const float* b_qkv  = (const float*)d_in[6];
    const float* W_proj = (const float*)d_in[7];
    const float* b_proj = (const float*)d_in[8];
    const float* W_fc   = (const float*)d_in[9];
    const float* b_fc   = (const float*)d_in[10];
    const float* W_out  = (const float*)d_in[11];
    const float* b_out  = (const float*)d_in[12];
    float* out = (float*)d_out;

    __nv_bfloat16 *h1h, *h1l, *qkvh, *qkvl, *atth, *attl, *h2h, *h2l, *fch, *fcl;
    __nv_bfloat16 *wqh, *wql, *wph, *wpl, *wfh, *wfl, *woh, *wol;
    float *x2;
    cudaGetSymbolAddress((void**)&h1h, g_h1_hi);  cudaGetSymbolAddress((void**)&h1l, g_h1_lo);
    cudaGetSymbolAddress((void**)&qkvh, g_qkv_hi); cudaGetSymbolAddress((void**)&qkvl, g_qkv_lo);
    cudaGetSymbolAddress((void**)&atth, g_att_hi); cudaGetSymbolAddress((void**)&attl, g_att_lo);
    cudaGetSymbolAddress((void**)&x2,  g_x2);
    cudaGetSymbolAddress((void**)&h2h, g_h2_hi);  cudaGetSymbolAddress((void**)&h2l, g_h2_lo);
    cudaGetSymbolAddress((void**)&fch, g_fc_hi);  cudaGetSymbolAddress((void**)&fcl, g_fc_lo);
    cudaGetSymbolAddress((void**)&wqh, g_wqkv_hi); cudaGetSymbolAddress((void**)&wql, g_wqkv_lo);
    cudaGetSymbolAddress((void**)&wph, g_wproj_hi); cudaGetSymbolAddress((void**)&wpl, g_wproj_lo);
    cudaGetSymbolAddress((void**)&wfh, g_wfc_hi);  cudaGetSymbolAddress((void**)&wfl, g_wfc_lo);
    cudaGetSymbolAddress((void**)&woh, g_wout_hi); cudaGetSymbolAddress((void**)&wol, g_wout_lo);

    cudaFuncSetAttribute(tc_gemm_kernel<0>, cudaFuncAttributeMaxDynamicSharedMemorySize, GEMM_SMEM);
    cudaFuncSetAttribute(tc_gemm_kernel<1>, cudaFuncAttributeMaxDynamicSharedMemorySize, GEMM_SMEM);
    cudaFuncSetAttribute(tc_gemm_kernel<2>, cudaFuncAttributeMaxDynamicSharedMemorySize, GEMM_SMEM);
    cudaFuncSetAttribute(tc_gemm_kernel<3>, cudaFuncAttributeMaxDynamicSharedMemorySize, GEMM_SMEM);
    cudaFuncSetAttribute(flash_kernel, cudaFuncAttributeMaxDynamicSharedMemorySize, FLASH_SMEM);

    // Weight transpose + split
    wconv_kernel<<<dim3(3 * DIM / 32, DIM / 32), 256>>>(W_qkv, wqh, wql, DIM, 3 * DIM);
    wconv_kernel<<<dim3(DIM / 32, DIM / 32), 256>>>(W_proj, wph, wpl, DIM, DIM);
    wconv_kernel<<<dim3(4 * DIM / 32, DIM / 32), 256>>>(W_fc, wfh, wfl, DIM, 4 * DIM);
    wconv_kernel<<<dim3(DIM / 32, 4 * DIM / 32), 256>>>(W_out, woh, wol, 4 * DIM, DIM);

    // 1) h1 = LN1(x) -> hi/lo
    ln_split_kernel<<<ROWS, 256>>>(x, ln1_g, ln1_b, h1h, h1l);

    // 2) qkv = h1 @ W_qkv + b_qkv -> hi/lo bf16 directly
    tc_gemm_kernel<3><<<dim3(3 * DIM / 128, ROWS / 128), 256, GEMM_SMEM>>>(
        h1h, h1l, wqh, wql, b_qkv, nullptr, nullptr, qkvh, qkvl, ROWS, 3 * DIM, DIM);

    // 3) att = causal_attention(qkv) -> hi/lo bf16 directly
    flash_kernel<<<dim3(SEQ / 64, BATCH * NHEAD), 128, FLASH_SMEM>>>(qkvh, qkvl, atth, attl);

    // 4) x2 = att @ W_proj + b_proj + x
    tc_gemm_kernel<1><<<dim3(DIM / 128, ROWS / 128), 256, GEMM_SMEM>>>(
        atth, attl, wph, wpl, b_proj, x, x2, nullptr, nullptr, ROWS, DIM, DIM);

    // 5) h2 = LN2(x2) -> hi/lo
    ln_split_kernel<<<ROWS, 256>>>(x2, ln2_g, ln2_b, h2h, h2l);

    // 6) fc = relu(h2 @ W_fc + b_fc) -> hi/lo
    tc_gemm_kernel<2><<<dim3(4 * DIM / 128, ROWS / 128), 256, GEMM_SMEM>>>(
        h2h, h2l, wfh, wfl, b_fc, nullptr, nullptr, fch, fcl, ROWS, 4 * DIM, DIM);

    // 7) out = fc @ W_out + b_out + x2
    tc_gemm_kernel<1><<<dim3(DIM / 128, ROWS / 128), 256, GEMM_SMEM>>>(
        fch, fcl, woh, wol, b_out, x2, out, nullptr, nullptr, ROWS, DIM, 4 * DIM);
}